// round 12
// baseline (speedup 1.0000x reference)
#include <cuda_runtime.h>
#include <cuda_bf16.h>
#include <cstdint>

#define D 64
#define MAX_NODES 100000
#define MAX_EDGES 1600000

// scratch (no cudaMalloc allowed)
__device__ __align__(16) __nv_bfloat16 g_nbr[(size_t)MAX_NODES * D];
__device__ __align__(16) __nv_bfloat16 g_embh[(size_t)MAX_NODES * D];
__device__ int g_deg[MAX_NODES];    // zero at load (.bss); re-zeroed by mlp each call
__device__ int g_off[MAX_NODES];
__device__ int g_cur[MAX_NODES];
__device__ int g_part[128];
__device__ int g_csr[MAX_EDGES];

static __device__ __forceinline__ uint32_t pack_bf2(float a, float b) {
    uint32_t r;
    asm("cvt.rn.bf16x2.f32 %0, %1, %2;" : "=r"(r) : "f"(b), "f"(a));  // lo=a, hi=b
    return r;
}

// ---------------------------------------------------------------------------
// K0 prep+hist: emb fp32 -> bf16, degree histogram, zero d_out.
// n_grp == n_edges == 1.6M: one index space covers both jobs.
// ---------------------------------------------------------------------------
__global__ __launch_bounds__(256) void prep_hist_kernel(
    const float* __restrict__ emb,
    const int* __restrict__ dst,
    float* __restrict__ out,
    int n_grp, int n_edges) {
    int i = blockIdx.x * blockDim.x + threadIdx.x;
    if (i < n_grp) {
        float4 v = __ldg(reinterpret_cast<const float4*>(emb) + i);
        uint2 pk;
        pk.x = pack_bf2(v.x, v.y);
        pk.y = pack_bf2(v.z, v.w);
        reinterpret_cast<uint2*>(g_embh)[i] = pk;
    }
    if (i < n_edges) {
        atomicAdd(&g_deg[__ldg(dst + i)], 1);
    }
    if (i < D / 4) reinterpret_cast<float4*>(out)[i] = make_float4(0.f, 0.f, 0.f, 0.f);
}

// ---------------------------------------------------------------------------
// K1 scan1: per-block (1024 elems) exclusive scan of g_deg -> g_off,
// block totals -> g_part. 256 threads x int4.
// ---------------------------------------------------------------------------
__global__ __launch_bounds__(256) void scan1_kernel(int n) {
    __shared__ int wsum[8];
    const int t = threadIdx.x;
    const int lane = t & 31, wid = t >> 5;
    const int base = blockIdx.x * 1024 + t * 4;

    int4 v = make_int4(0, 0, 0, 0);
    if (base < n) v = __ldg(reinterpret_cast<const int4*>(g_deg + base));  // n % 4 == 0
    int s = v.x + v.y + v.z + v.w;

    // warp exclusive scan of thread sums
    int pre = s;
    #pragma unroll
    for (int o = 1; o < 32; o <<= 1) {
        int x = __shfl_up_sync(0xffffffffu, pre, o);
        if (lane >= o) pre += x;
    }
    pre -= s;   // exclusive
    if (lane == 31) wsum[wid] = pre + s;
    __syncthreads();
    if (wid == 0 && lane < 8) {
        int ws = wsum[lane];
        int wp = ws;
        #pragma unroll
        for (int o = 1; o < 8; o <<= 1) {
            int x = __shfl_up_sync(0x000000ffu, wp, o);
            if (lane >= o) wp += x;
        }
        wsum[lane] = wp - ws;   // exclusive warp base
    }
    __syncthreads();
    int ebase = wsum[wid] + pre;

    if (base < n) {
        int4 o4;
        o4.x = ebase;
        o4.y = ebase + v.x;
        o4.z = o4.y + v.y;
        o4.w = o4.z + v.z;
        *reinterpret_cast<int4*>(g_off + base) = o4;
    }
    if (t == 255) g_part[blockIdx.x] = ebase + s;   // block total
}

// ---------------------------------------------------------------------------
// K2 scan2+apply: add prefix of block partials, write g_off and g_cur.
// ---------------------------------------------------------------------------
__global__ __launch_bounds__(256) void scan2_kernel(int n, int nb) {
    __shared__ int pref_s;
    const int t = threadIdx.x;
    if (t == 0) {
        int p = 0;
        for (int j = 0; j < (int)blockIdx.x; j++) p += g_part[j];   // nb <= 98
        pref_s = p;
    }
    __syncthreads();
    const int pref = pref_s;
    const int base = blockIdx.x * 1024 + t * 4;
    if (base < n) {
        int4 o = *reinterpret_cast<const int4*>(g_off + base);
        o.x += pref; o.y += pref; o.z += pref; o.w += pref;
        *reinterpret_cast<int4*>(g_off + base) = o;
        *reinterpret_cast<int4*>(g_cur + base) = o;
    }
    (void)nb;
}

// ---------------------------------------------------------------------------
// K3 fill: csr[cursor(dst)++] = src. 4 edges/thread via int4 loads.
// ---------------------------------------------------------------------------
__global__ __launch_bounds__(256) void fill_kernel(const int* __restrict__ src,
                                                   const int* __restrict__ dst,
                                                   int n_e4) {
    int i = blockIdx.x * blockDim.x + threadIdx.x;
    int stride = gridDim.x * blockDim.x;
    for (; i < n_e4; i += stride) {
        int4 s4 = __ldg(reinterpret_cast<const int4*>(src) + i);
        int4 d4 = __ldg(reinterpret_cast<const int4*>(dst) + i);
        g_csr[atomicAdd(&g_cur[d4.x], 1)] = s4.x;
        g_csr[atomicAdd(&g_cur[d4.y], 1)] = s4.y;
        g_csr[atomicAdd(&g_cur[d4.z], 1)] = s4.z;
        g_csr[atomicAdd(&g_cur[d4.w], 1)] = s4.w;
    }
}

// ---------------------------------------------------------------------------
// K4 gather: warp per node. nbr[v] = sum_j emb_bf16[csr[off[v]+j]].
// fp32 accumulate (2 dims/lane), one bf16 round at the end. No atomics.
// ---------------------------------------------------------------------------
__global__ __launch_bounds__(256) void gather_kernel(int n_nodes, int n_edges) {
    int w = (blockIdx.x * blockDim.x + threadIdx.x) >> 5;
    int lane = threadIdx.x & 31;
    if (w >= n_nodes) return;
    int j = g_off[w];
    const int end = (w + 1 < n_nodes) ? g_off[w + 1] : n_edges;

    float a0 = 0.f, b0 = 0.f, a1 = 0.f, b1v = 0.f;
    const uint32_t* embu = reinterpret_cast<const uint32_t*>(g_embh);

    for (; j + 4 <= end; j += 4) {
        int s0 = __ldg(g_csr + j);
        int s1 = __ldg(g_csr + j + 1);
        int s2 = __ldg(g_csr + j + 2);
        int s3 = __ldg(g_csr + j + 3);
        uint32_t u0 = __ldg(embu + (size_t)s0 * 32 + lane);
        uint32_t u1 = __ldg(embu + (size_t)s1 * 32 + lane);
        uint32_t u2 = __ldg(embu + (size_t)s2 * 32 + lane);
        uint32_t u3 = __ldg(embu + (size_t)s3 * 32 + lane);
        a0  += __uint_as_float(u0 << 16);
        b0  += __uint_as_float(u0 & 0xffff0000u);
        a1  += __uint_as_float(u1 << 16);
        b1v += __uint_as_float(u1 & 0xffff0000u);
        a0  += __uint_as_float(u2 << 16);
        b0  += __uint_as_float(u2 & 0xffff0000u);
        a1  += __uint_as_float(u3 << 16);
        b1v += __uint_as_float(u3 & 0xffff0000u);
    }
    for (; j < end; j++) {
        int s = __ldg(g_csr + j);
        uint32_t u = __ldg(embu + (size_t)s * 32 + lane);
        a0 += __uint_as_float(u << 16);
        b0 += __uint_as_float(u & 0xffff0000u);
    }
    reinterpret_cast<uint32_t*>(g_nbr)[(size_t)w * 32 + lane] = pack_bf2(a0 + a1, b0 + b1v);
}

// ---------------------------------------------------------------------------
// K5: HMMA MLP + relu + graph-sum (proven ~2.4us) + re-zero g_deg for the
// next graph replay (deterministic: every call sees zeroed g_deg).
// ---------------------------------------------------------------------------
#define MLP_BLOCKS 592
#define RSTRIDE 272

#define LDSM_X4(r0, r1, r2, r3, addr) \
    asm volatile("ldmatrix.sync.aligned.m8n8.x4.shared.b16 {%0,%1,%2,%3}, [%4];" \
                 : "=r"(r0), "=r"(r1), "=r"(r2), "=r"(r3) : "r"(addr))

#define MMA_BF16(c0, c1, c2, c3, a0, a1, a2, a3, b0, b1) \
    asm volatile("mma.sync.aligned.m16n8k16.row.col.f32.bf16.bf16.f32 " \
                 "{%0,%1,%2,%3}, {%4,%5,%6,%7}, {%8,%9}, {%0,%1,%2,%3};" \
                 : "+f"(c0), "+f"(c1), "+f"(c2), "+f"(c3) \
                 : "r"(a0), "r"(a1), "r"(a2), "r"(a3), "r"(b0), "r"(b1))

__global__ __launch_bounds__(128) void mlp_hmma_kernel(
    const float* __restrict__ feat,
    const float* __restrict__ W1,
    const float* __restrict__ b1,
    const float* __restrict__ W2,
    const float* __restrict__ b2,
    float* __restrict__ out,
    int n_nodes) {

    __shared__ __align__(16) char As[64 * RSTRIDE];
    __shared__ __align__(16) char Bs[64 * RSTRIDE];
    __shared__ float bias[D];
    __shared__ float red[4][D];

    const int t = threadIdx.x;
    const int w = t >> 5;
    const int l = t & 31;

    // re-zero degree counters for next replay
    for (int i = blockIdx.x * 128 + t; i < n_nodes; i += MLP_BLOCKS * 128)
        g_deg[i] = 0;

    for (int i = t; i < 1024; i += 128) {
        int o = i >> 4, kg = i & 15;
        float4 a = __ldg(reinterpret_cast<const float4*>(W1) + o * 16 + kg);
        float4 b = __ldg(reinterpret_cast<const float4*>(W2) + o * 16 + kg);
        uint2 pa, pb;
        pa.x = pack_bf2(a.x, a.y); pa.y = pack_bf2(a.z, a.w);
        pb.x = pack_bf2(b.x, b.y); pb.y = pack_bf2(b.z, b.w);
        *reinterpret_cast<uint2*>(Bs + o * RSTRIDE + kg * 8) = pa;
        *reinterpret_cast<uint2*>(Bs + o * RSTRIDE + 128 + kg * 8) = pb;
    }
    if (t < D) bias[t] = __ldg(b1 + t) + __ldg(b2 + t);
    __syncthreads();

    float biasr[8][2];
    #pragma unroll
    for (int f = 0; f < 8; f++) {
        int c0 = f * 8 + (l & 3) * 2;
        biasr[f][0] = bias[c0];
        biasr[f][1] = bias[c0 + 1];
    }

    float colsum[8][2];
    #pragma unroll
    for (int f = 0; f < 8; f++) { colsum[f][0] = 0.f; colsum[f][1] = 0.f; }

    const uint32_t As_u = (uint32_t)__cvta_generic_to_shared(As);
    const uint32_t Bs_u = (uint32_t)__cvta_generic_to_shared(Bs);
    const int quad = l >> 2;

    const int n_tiles = (n_nodes + 63) >> 6;
    for (int tile = blockIdx.x; tile < n_tiles; tile += gridDim.x) {
        const int base = tile << 6;
        __syncthreads();

        #pragma unroll
        for (int j = 0; j < 8; j++) {
            int idx = t + j * 128;
            int row = idx >> 4, kg = idx & 15;
            int v = base + row;
            uint2 p = make_uint2(0u, 0u);
            if (v < n_nodes) {
                float4 x = __ldg(reinterpret_cast<const float4*>(feat) + (size_t)v * 16 + kg);
                p.x = pack_bf2(x.x, x.y);
                p.y = pack_bf2(x.z, x.w);
            }
            *reinterpret_cast<uint2*>(As + row * RSTRIDE + kg * 8) = p;
        }
        #pragma unroll
        for (int j = 0; j < 4; j++) {
            int idx = t + j * 128;
            int row = idx >> 3, c = idx & 7;
            int v = base + row;
            uint4 u = (v < n_nodes)
                ? *(reinterpret_cast<const uint4*>(g_nbr) + (size_t)v * 8 + c)
                : make_uint4(0u, 0u, 0u, 0u);
            *reinterpret_cast<uint4*>(As + row * RSTRIDE + 128 + c * 16) = u;
        }
        __syncthreads();

        float acc[8][4];
        #pragma unroll
        for (int f = 0; f < 8; f++)
            #pragma unroll
            for (int q = 0; q < 4; q++) acc[f][q] = 0.f;

        #pragma unroll
        for (int s2 = 0; s2 < 4; s2++) {
            uint32_t a0[4], a1[4];
            uint32_t arow = As_u + (w * 16 + (l & 15)) * RSTRIDE + s2 * 64 + ((l >> 4) << 4);
            LDSM_X4(a0[0], a0[1], a0[2], a0[3], arow);
            LDSM_X4(a1[0], a1[1], a1[2], a1[3], arow + 32);
            #pragma unroll
            for (int f = 0; f < 8; f++) {
                uint32_t b[4];
                uint32_t baddr = Bs_u + (f * 8 + (l & 7)) * RSTRIDE + s2 * 64 + ((l >> 3) & 3) * 16;
                LDSM_X4(b[0], b[1], b[2], b[3], baddr);
                MMA_BF16(acc[f][0], acc[f][1], acc[f][2], acc[f][3],
                         a0[0], a0[1], a0[2], a0[3], b[0], b[1]);
                MMA_BF16(acc[f][0], acc[f][1], acc[f][2], acc[f][3],
                         a1[0], a1[1], a1[2], a1[3], b[2], b[3]);
            }
        }

        const bool vlo = (base + w * 16 + quad) < n_nodes;
        const bool vhi = (base + w * 16 + quad + 8) < n_nodes;
        #pragma unroll
        for (int f = 0; f < 8; f++) {
            if (vlo) {
                colsum[f][0] += fmaxf(acc[f][0] + biasr[f][0], 0.f);
                colsum[f][1] += fmaxf(acc[f][1] + biasr[f][1], 0.f);
            }
            if (vhi) {
                colsum[f][0] += fmaxf(acc[f][2] + biasr[f][0], 0.f);
                colsum[f][1] += fmaxf(acc[f][3] + biasr[f][1], 0.f);
            }
        }
    }

    #pragma unroll
    for (int f = 0; f < 8; f++) {
        #pragma unroll
        for (int j = 0; j < 2; j++) {
            float v = colsum[f][j];
            v += __shfl_xor_sync(0xffffffffu, v, 4);
            v += __shfl_xor_sync(0xffffffffu, v, 8);
            v += __shfl_xor_sync(0xffffffffu, v, 16);
            colsum[f][j] = v;
        }
    }
    if (l < 4) {
        #pragma unroll
        for (int f = 0; f < 8; f++) {
            red[w][f * 8 + l * 2 + 0] = colsum[f][0];
            red[w][f * 8 + l * 2 + 1] = colsum[f][1];
        }
    }
    __syncthreads();
    if (t < D) {
        atomicAdd(out + t, red[0][t] + red[1][t] + red[2][t] + red[3][t]);
    }
}

// ---------------------------------------------------------------------------
// launch — inputs (metadata order): feat, emb, W1, b1, W2, b2, edge_src, edge_dst
// Order: prep(0), scan1(1), scan2(2), fill(3)<-ncu idx 3, gather(4), mlp(5).
// ---------------------------------------------------------------------------
extern "C" void kernel_launch(void* const* d_in, const int* in_sizes, int n_in,
                              void* d_out, int out_size) {
    (void)n_in; (void)out_size;
    const float* feat = (const float*)d_in[0];
    const float* emb  = (const float*)d_in[1];
    const float* W1   = (const float*)d_in[2];
    const float* b1   = (const float*)d_in[3];
    const float* W2   = (const float*)d_in[4];
    const float* b2   = (const float*)d_in[5];
    const int* esrc   = (const int*)d_in[6];
    const int* edst   = (const int*)d_in[7];
    float* out        = (float*)d_out;

    const int n_nodes = in_sizes[0] / D;
    const int n_edges = in_sizes[6];

    // K0 prep + hist
    {
        int n_grp = n_nodes * (D / 4);
        int n_max = n_grp > n_edges ? n_grp : n_edges;
        prep_hist_kernel<<<(n_max + 255) / 256, 256>>>(emb, edst, out, n_grp, n_edges);
    }
    // K1/K2 scan
    int nb = (n_nodes + 1023) / 1024;
    scan1_kernel<<<nb, 256>>>(n_nodes);
    scan2_kernel<<<nb, 256>>>(n_nodes, nb);
    // K3 CSR fill
    fill_kernel<<<2048, 256>>>(esrc, edst, n_edges / 4);
    // K4 gather (no atomics)
    gather_kernel<<<(n_nodes * 32 + 255) / 256, 256>>>(n_nodes, n_edges);
    // K5 HMMA MLP + graph reduce + deg re-zero
    mlp_hmma_kernel<<<MLP_BLOCKS, 128>>>(feat, W1, b1, W2, b2, out, n_nodes);
}

// round 13
// speedup vs baseline: 1.0546x; 1.0546x over previous
#include <cuda_runtime.h>
#include <cuda_bf16.h>
#include <cstdint>

#define D 64
#define MAX_NODES 100000
#define MAX_EDGES 1600000

// scratch (no cudaMalloc allowed)
__device__ __align__(16) __nv_bfloat16 g_nbr[(size_t)MAX_NODES * D];
__device__ __align__(16) __nv_bfloat16 g_embh[(size_t)MAX_NODES * D];
__device__ int g_deg[MAX_NODES];    // zeroed at load (.bss); re-zeroed by mlp
__device__ int g_off[MAX_NODES];
__device__ int g_cur[MAX_NODES];
__device__ int g_stat[128];         // lookback: (status<<28)|sum ; re-zeroed by mlp
__device__ int g_csr[MAX_EDGES];

static __device__ __forceinline__ uint32_t pack_bf2(float a, float b) {
    uint32_t r;
    asm("cvt.rn.bf16x2.f32 %0, %1, %2;" : "=r"(r) : "f"(b), "f"(a));  // lo=a, hi=b
    return r;
}

// ---------------------------------------------------------------------------
// K0 prep+hist: emb fp32 -> bf16, REDG degree histogram, zero d_out.
// ---------------------------------------------------------------------------
__global__ __launch_bounds__(256) void prep_hist_kernel(
    const float* __restrict__ emb,
    const int* __restrict__ dst,
    float* __restrict__ out,
    int n_grp, int n_edges) {
    int i = blockIdx.x * blockDim.x + threadIdx.x;
    if (i < n_grp) {
        float4 v = __ldg(reinterpret_cast<const float4*>(emb) + i);
        uint2 pk;
        pk.x = pack_bf2(v.x, v.y);
        pk.y = pack_bf2(v.z, v.w);
        reinterpret_cast<uint2*>(g_embh)[i] = pk;
    }
    if (i < n_edges) {
        int* p = &g_deg[__ldg(dst + i)];
        asm volatile("red.global.add.u32 [%0], 1;" :: "l"(p) : "memory");
    }
    if (i < D / 4) reinterpret_cast<float4*>(out)[i] = make_float4(0.f, 0.f, 0.f, 0.f);
}

// ---------------------------------------------------------------------------
// K1 scan: single-kernel exclusive prefix sum via decoupled lookback.
// 98 blocks x 1024 elems. Status+value packed in one 32-bit word
// (sums <= 1.6M < 2^28): 0 = pending, 1<<28 = aggregate, 2<<28 = inclusive.
// Writes g_off and g_cur.
// ---------------------------------------------------------------------------
__global__ __launch_bounds__(256) void scan_kernel(int n) {
    __shared__ int wsum[8];
    __shared__ int pref_s;
    const int t = threadIdx.x;
    const int lane = t & 31, wid = t >> 5;
    const int bid = blockIdx.x;
    const int base = bid * 1024 + t * 4;

    int4 v = make_int4(0, 0, 0, 0);
    if (base < n) v = __ldg(reinterpret_cast<const int4*>(g_deg + base));  // n % 4 == 0
    int s = v.x + v.y + v.z + v.w;

    // warp inclusive scan of thread sums -> exclusive
    int pre = s;
    #pragma unroll
    for (int o = 1; o < 32; o <<= 1) {
        int x = __shfl_up_sync(0xffffffffu, pre, o);
        if (lane >= o) pre += x;
    }
    pre -= s;
    if (lane == 31) wsum[wid] = pre + s;
    __syncthreads();
    if (wid == 0 && lane < 8) {
        int ws = wsum[lane];
        int wp = ws;
        #pragma unroll
        for (int o = 1; o < 8; o <<= 1) {
            int x = __shfl_up_sync(0x000000ffu, wp, o);
            if (lane >= o) wp += x;
        }
        wsum[lane] = wp - ws;
    }
    __syncthreads();
    const int ebase = wsum[wid] + pre;          // exclusive within block

    // thread 255 knows the block total
    if (t == 255) {
        int total = ebase + s;
        if (bid == 0) {
            atomicExch(&g_stat[0], (2 << 28) | total);       // inclusive
            pref_s = 0;
        } else {
            atomicExch(&g_stat[bid], (1 << 28) | total);     // aggregate
            // lookback
            int acc = 0;
            int j = bid - 1;
            while (j >= 0) {
                int w;
                do { w = atomicAdd(&g_stat[j], 0); } while ((w >> 28) == 0);
                acc += w & 0x0fffffff;
                if ((w >> 28) == 2) break;
                j--;
            }
            atomicExch(&g_stat[bid], (2 << 28) | (acc + total));
            pref_s = acc;
        }
    }
    __syncthreads();
    const int pref = pref_s;

    if (base < n) {
        int4 o4;
        o4.x = pref + ebase;
        o4.y = o4.x + v.x;
        o4.z = o4.y + v.y;
        o4.w = o4.z + v.z;
        *reinterpret_cast<int4*>(g_off + base) = o4;
        *reinterpret_cast<int4*>(g_cur + base) = o4;
    }
}

// ---------------------------------------------------------------------------
// K2 fill: csr[cursor(dst)++] = src. 4 edges/thread via int4 loads.
// (ATOMG-with-return floor ~23us; structural, left as-is this round.)
// ---------------------------------------------------------------------------
__global__ __launch_bounds__(256) void fill_kernel(const int* __restrict__ src,
                                                   const int* __restrict__ dst,
                                                   int n_e4) {
    int i = blockIdx.x * blockDim.x + threadIdx.x;
    int stride = gridDim.x * blockDim.x;
    for (; i < n_e4; i += stride) {
        int4 s4 = __ldg(reinterpret_cast<const int4*>(src) + i);
        int4 d4 = __ldg(reinterpret_cast<const int4*>(dst) + i);
        int p0 = atomicAdd(&g_cur[d4.x], 1);
        int p1 = atomicAdd(&g_cur[d4.y], 1);
        int p2 = atomicAdd(&g_cur[d4.z], 1);
        int p3 = atomicAdd(&g_cur[d4.w], 1);
        g_csr[p0] = s4.x;
        g_csr[p1] = s4.y;
        g_csr[p2] = s4.z;
        g_csr[p3] = s4.w;
    }
}

// ---------------------------------------------------------------------------
// K3 gather (PROFILED, launch idx 3): HALF-WARP per node.
// 16 lanes x uint2 (8B) = 128B row; 4-edge unroll -> 8 loads in flight/warp,
// half the warp count of warp-per-node. fp32 accumulate, bf16 round once.
// ---------------------------------------------------------------------------
__global__ __launch_bounds__(256) void gather_kernel(int n_nodes, int n_edges) {
    const int hw = (blockIdx.x * blockDim.x + threadIdx.x) >> 4;   // half-warp id = node
    const int lane = threadIdx.x & 15;
    if (hw >= n_nodes) return;
    int j = __ldg(g_off + hw);
    const int end = (hw + 1 < n_nodes) ? __ldg(g_off + hw + 1) : n_edges;

    // 4 fp32 accumulators (uint2 = 4 bf16 dims per lane)
    float a0 = 0.f, a1 = 0.f, a2 = 0.f, a3 = 0.f;
    const uint2* embu = reinterpret_cast<const uint2*>(g_embh);

    for (; j + 4 <= end; j += 4) {
        int s0 = __ldg(g_csr + j);
        int s1 = __ldg(g_csr + j + 1);
        int s2 = __ldg(g_csr + j + 2);
        int s3 = __ldg(g_csr + j + 3);
        uint2 u0 = __ldg(embu + (size_t)s0 * 16 + lane);
        uint2 u1 = __ldg(embu + (size_t)s1 * 16 + lane);
        uint2 u2 = __ldg(embu + (size_t)s2 * 16 + lane);
        uint2 u3 = __ldg(embu + (size_t)s3 * 16 + lane);
        a0 += __uint_as_float(u0.x << 16);
        a1 += __uint_as_float(u0.x & 0xffff0000u);
        a2 += __uint_as_float(u0.y << 16);
        a3 += __uint_as_float(u0.y & 0xffff0000u);
        a0 += __uint_as_float(u1.x << 16);
        a1 += __uint_as_float(u1.x & 0xffff0000u);
        a2 += __uint_as_float(u1.y << 16);
        a3 += __uint_as_float(u1.y & 0xffff0000u);
        a0 += __uint_as_float(u2.x << 16);
        a1 += __uint_as_float(u2.x & 0xffff0000u);
        a2 += __uint_as_float(u2.y << 16);
        a3 += __uint_as_float(u2.y & 0xffff0000u);
        a0 += __uint_as_float(u3.x << 16);
        a1 += __uint_as_float(u3.x & 0xffff0000u);
        a2 += __uint_as_float(u3.y << 16);
        a3 += __uint_as_float(u3.y & 0xffff0000u);
    }
    for (; j < end; j++) {
        int s = __ldg(g_csr + j);
        uint2 u = __ldg(embu + (size_t)s * 16 + lane);
        a0 += __uint_as_float(u.x << 16);
        a1 += __uint_as_float(u.x & 0xffff0000u);
        a2 += __uint_as_float(u.y << 16);
        a3 += __uint_as_float(u.y & 0xffff0000u);
    }
    uint2 r;
    r.x = pack_bf2(a0, a1);
    r.y = pack_bf2(a2, a3);
    reinterpret_cast<uint2*>(g_nbr)[(size_t)hw * 16 + lane] = r;
}

// ---------------------------------------------------------------------------
// K4: HMMA MLP + relu + graph-sum (proven ~2.4us) + reset g_deg/g_stat
// for the next replay.
// ---------------------------------------------------------------------------
#define MLP_BLOCKS 592
#define RSTRIDE 272

#define LDSM_X4(r0, r1, r2, r3, addr) \
    asm volatile("ldmatrix.sync.aligned.m8n8.x4.shared.b16 {%0,%1,%2,%3}, [%4];" \
                 : "=r"(r0), "=r"(r1), "=r"(r2), "=r"(r3) : "r"(addr))

#define MMA_BF16(c0, c1, c2, c3, a0, a1, a2, a3, b0, b1) \
    asm volatile("mma.sync.aligned.m16n8k16.row.col.f32.bf16.bf16.f32 " \
                 "{%0,%1,%2,%3}, {%4,%5,%6,%7}, {%8,%9}, {%0,%1,%2,%3};" \
                 : "+f"(c0), "+f"(c1), "+f"(c2), "+f"(c3) \
                 : "r"(a0), "r"(a1), "r"(a2), "r"(a3), "r"(b0), "r"(b1))

__global__ __launch_bounds__(128) void mlp_hmma_kernel(
    const float* __restrict__ feat,
    const float* __restrict__ W1,
    const float* __restrict__ b1,
    const float* __restrict__ W2,
    const float* __restrict__ b2,
    float* __restrict__ out,
    int n_nodes) {

    __shared__ __align__(16) char As[64 * RSTRIDE];
    __shared__ __align__(16) char Bs[64 * RSTRIDE];
    __shared__ float bias[D];
    __shared__ float red[4][D];

    const int t = threadIdx.x;
    const int w = t >> 5;
    const int l = t & 31;

    // reset scratch for next replay
    for (int i = blockIdx.x * 128 + t; i < n_nodes; i += MLP_BLOCKS * 128)
        g_deg[i] = 0;
    if (blockIdx.x == 0 && t < 128) g_stat[t] = 0;

    for (int i = t; i < 1024; i += 128) {
        int o = i >> 4, kg = i & 15;
        float4 a = __ldg(reinterpret_cast<const float4*>(W1) + o * 16 + kg);
        float4 b = __ldg(reinterpret_cast<const float4*>(W2) + o * 16 + kg);
        uint2 pa, pb;
        pa.x = pack_bf2(a.x, a.y); pa.y = pack_bf2(a.z, a.w);
        pb.x = pack_bf2(b.x, b.y); pb.y = pack_bf2(b.z, b.w);
        *reinterpret_cast<uint2*>(Bs + o * RSTRIDE + kg * 8) = pa;
        *reinterpret_cast<uint2*>(Bs + o * RSTRIDE + 128 + kg * 8) = pb;
    }
    if (t < D) bias[t] = __ldg(b1 + t) + __ldg(b2 + t);
    __syncthreads();

    float biasr[8][2];
    #pragma unroll
    for (int f = 0; f < 8; f++) {
        int c0 = f * 8 + (l & 3) * 2;
        biasr[f][0] = bias[c0];
        biasr[f][1] = bias[c0 + 1];
    }

    float colsum[8][2];
    #pragma unroll
    for (int f = 0; f < 8; f++) { colsum[f][0] = 0.f; colsum[f][1] = 0.f; }

    const uint32_t As_u = (uint32_t)__cvta_generic_to_shared(As);
    const uint32_t Bs_u = (uint32_t)__cvta_generic_to_shared(Bs);
    const int quad = l >> 2;

    const int n_tiles = (n_nodes + 63) >> 6;
    for (int tile = blockIdx.x; tile < n_tiles; tile += gridDim.x) {
        const int base = tile << 6;
        __syncthreads();

        #pragma unroll
        for (int j = 0; j < 8; j++) {
            int idx = t + j * 128;
            int row = idx >> 4, kg = idx & 15;
            int v = base + row;
            uint2 p = make_uint2(0u, 0u);
            if (v < n_nodes) {
                float4 x = __ldg(reinterpret_cast<const float4*>(feat) + (size_t)v * 16 + kg);
                p.x = pack_bf2(x.x, x.y);
                p.y = pack_bf2(x.z, x.w);
            }
            *reinterpret_cast<uint2*>(As + row * RSTRIDE + kg * 8) = p;
        }
        #pragma unroll
        for (int j = 0; j < 4; j++) {
            int idx = t + j * 128;
            int row = idx >> 3, c = idx & 7;
            int v = base + row;
            uint4 u = (v < n_nodes)
                ? *(reinterpret_cast<const uint4*>(g_nbr) + (size_t)v * 8 + c)
                : make_uint4(0u, 0u, 0u, 0u);
            *reinterpret_cast<uint4*>(As + row * RSTRIDE + 128 + c * 16) = u;
        }
        __syncthreads();

        float acc[8][4];
        #pragma unroll
        for (int f = 0; f < 8; f++)
            #pragma unroll
            for (int q = 0; q < 4; q++) acc[f][q] = 0.f;

        #pragma unroll
        for (int s2 = 0; s2 < 4; s2++) {
            uint32_t a0[4], a1[4];
            uint32_t arow = As_u + (w * 16 + (l & 15)) * RSTRIDE + s2 * 64 + ((l >> 4) << 4);
            LDSM_X4(a0[0], a0[1], a0[2], a0[3], arow);
            LDSM_X4(a1[0], a1[1], a1[2], a1[3], arow + 32);
            #pragma unroll
            for (int f = 0; f < 8; f++) {
                uint32_t b[4];
                uint32_t baddr = Bs_u + (f * 8 + (l & 7)) * RSTRIDE + s2 * 64 + ((l >> 3) & 3) * 16;
                LDSM_X4(b[0], b[1], b[2], b[3], baddr);
                MMA_BF16(acc[f][0], acc[f][1], acc[f][2], acc[f][3],
                         a0[0], a0[1], a0[2], a0[3], b[0], b[1]);
                MMA_BF16(acc[f][0], acc[f][1], acc[f][2], acc[f][3],
                         a1[0], a1[1], a1[2], a1[3], b[2], b[3]);
            }
        }

        const bool vlo = (base + w * 16 + quad) < n_nodes;
        const bool vhi = (base + w * 16 + quad + 8) < n_nodes;
        #pragma unroll
        for (int f = 0; f < 8; f++) {
            if (vlo) {
                colsum[f][0] += fmaxf(acc[f][0] + biasr[f][0], 0.f);
                colsum[f][1] += fmaxf(acc[f][1] + biasr[f][1], 0.f);
            }
            if (vhi) {
                colsum[f][0] += fmaxf(acc[f][2] + biasr[f][0], 0.f);
                colsum[f][1] += fmaxf(acc[f][3] + biasr[f][1], 0.f);
            }
        }
    }

    #pragma unroll
    for (int f = 0; f < 8; f++) {
        #pragma unroll
        for (int j = 0; j < 2; j++) {
            float v = colsum[f][j];
            v += __shfl_xor_sync(0xffffffffu, v, 4);
            v += __shfl_xor_sync(0xffffffffu, v, 8);
            v += __shfl_xor_sync(0xffffffffu, v, 16);
            colsum[f][j] = v;
        }
    }
    if (l < 4) {
        #pragma unroll
        for (int f = 0; f < 8; f++) {
            red[w][f * 8 + l * 2 + 0] = colsum[f][0];
            red[w][f * 8 + l * 2 + 1] = colsum[f][1];
        }
    }
    __syncthreads();
    if (t < D) {
        atomicAdd(out + t, red[0][t] + red[1][t] + red[2][t] + red[3][t]);
    }
}

// ---------------------------------------------------------------------------
// launch — inputs (metadata order): feat, emb, W1, b1, W2, b2, edge_src, edge_dst
// Order: prep_hist(0), scan(1), fill(2), gather(3)<-ncu idx 3, mlp(4).
// ---------------------------------------------------------------------------
extern "C" void kernel_launch(void* const* d_in, const int* in_sizes, int n_in,
                              void* d_out, int out_size) {
    (void)n_in; (void)out_size;
    const float* feat = (const float*)d_in[0];
    const float* emb  = (const float*)d_in[1];
    const float* W1   = (const float*)d_in[2];
    const float* b1   = (const float*)d_in[3];
    const float* W2   = (const float*)d_in[4];
    const float* b2   = (const float*)d_in[5];
    const int* esrc   = (const int*)d_in[6];
    const int* edst   = (const int*)d_in[7];
    float* out        = (float*)d_out;

    const int n_nodes = in_sizes[0] / D;
    const int n_edges = in_sizes[6];

    // K0 prep + hist
    {
        int n_grp = n_nodes * (D / 4);
        int n_max = n_grp > n_edges ? n_grp : n_edges;
        prep_hist_kernel<<<(n_max + 255) / 256, 256>>>(emb, edst, out, n_grp, n_edges);
    }
    // K1 single-kernel lookback scan
    scan_kernel<<<(n_nodes + 1023) / 1024, 256>>>(n_nodes);
    // K2 CSR fill
    fill_kernel<<<2048, 256>>>(esrc, edst, n_edges / 4);
    // K3 gather (half-warp per node) — profiled
    gather_kernel<<<(n_nodes * 16 + 255) / 256, 256>>>(n_nodes, n_edges);
    // K4 HMMA MLP + graph reduce + scratch reset
    mlp_hmma_kernel<<<MLP_BLOCKS, 128>>>(feat, W1, b1, W2, b2, out, n_nodes);
}